// round 3
// baseline (speedup 1.0000x reference)
#include <cuda_runtime.h>
#include <cuda_fp16.h>
#include <math.h>

#define NPTS (1 << 20)
#define RES 128
#define LDW 264   // padded K-stride (halves) for 256-wide operands: bank-conflict-free
#define LDW0 56   // padded K-stride for the 48-wide layer-0 input

// Scratch activations (device globals: allocation-free per harness rules)
static __device__ __half g_h1[(size_t)NPTS * 256];
static __device__ __half g_h2[(size_t)NPTS * 256];

__device__ __forceinline__ void mma16816(float c[4], const unsigned a[4], const unsigned b[2]) {
    asm volatile(
        "mma.sync.aligned.m16n8k16.row.col.f32.f16.f16.f32 "
        "{%0,%1,%2,%3},{%4,%5,%6,%7},{%8,%9},{%0,%1,%2,%3};\n"
        : "+f"(c[0]), "+f"(c[1]), "+f"(c[2]), "+f"(c[3])
        : "r"(a[0]), "r"(a[1]), "r"(a[2]), "r"(a[3]), "r"(b[0]), "r"(b[1]));
}

// Warp computes a 16(m) x 128(n) tile: A row-major (lda in halves), W transposed
// in smem as Wt[n][k] row-major with stride ldw (= col-major B for mma).
template <int KDIM>
__device__ __forceinline__ void gemm_warp(const __half* A, int lda,
                                          const __half* Wt, int ldw,
                                          int m0, int n0, int lane,
                                          float acc[16][4]) {
    const int g = lane >> 2, r = lane & 3;
    for (int k0 = 0; k0 < KDIM; k0 += 16) {
        unsigned a[4];
        const __half* ap = A + (size_t)(m0 + g) * lda + k0 + r * 2;
        a[0] = *(const unsigned*)(ap);
        a[1] = *(const unsigned*)(ap + (size_t)8 * lda);
        a[2] = *(const unsigned*)(ap + 8);
        a[3] = *(const unsigned*)(ap + (size_t)8 * lda + 8);
#pragma unroll
        for (int t = 0; t < 16; t++) {
            const __half* bp = Wt + (size_t)(n0 + t * 8 + g) * ldw + k0 + r * 2;
            unsigned b[2];
            b[0] = *(const unsigned*)(bp);
            b[1] = *(const unsigned*)(bp + 8);
            mma16816(acc[t], a, b);
        }
    }
}

// ============================================================================
// K1: encode (tri-plane gather + PE) + layer0 (47->256) + layer1 (256->256)
// 256 threads, M-tile = 64, persistent.
// ============================================================================
extern __shared__ char smem_raw[];

__global__ void __launch_bounds__(256, 1) k_enc01(
    const float* __restrict__ x,
    const float* __restrict__ fxy, const float* __restrict__ fxz, const float* __restrict__ fyz,
    const float* __restrict__ W0, const float* __restrict__ b0,
    const float* __restrict__ W1, const float* __restrict__ b1,
    __half* __restrict__ h1_out) {
    __half* Wt0 = (__half*)smem_raw;                 // 256*56 halves
    __half* Wt1 = Wt0 + 256 * LDW0;                  // 256*264 halves
    float*  b0s = (float*)(Wt1 + 256 * LDW);         // 256 f32
    float*  b1s = b0s + 256;                         // 256 f32
    __half* A0  = (__half*)(b1s + 256);              // 64*56 halves
    __half* H   = A0 + 64 * LDW0;                    // 64*264 halves

    const int tid = threadIdx.x;

    // One-time: transpose weights to fp16 smem, load biases.
    for (int i = tid; i < 48 * 256; i += 256) {
        int k = i >> 8, n = i & 255;
        Wt0[n * LDW0 + k] = __float2half(k < 47 ? W0[k * 256 + n] : 0.f);
    }
    for (int i = tid; i < 256 * 256; i += 256) {
        int k = i >> 8, n = i & 255;
        Wt1[n * LDW + k] = __float2half(W1[k * 256 + n]);
    }
    if (tid < 256) { b0s[tid] = b0[tid]; b1s[tid] = b1[tid]; }
    __syncthreads();

    const int wid = tid >> 5, lane = tid & 31;
    const int m0 = (wid >> 1) * 16, n0 = (wid & 1) * 128;
    const int g = lane >> 2, r = lane & 3;

    for (int tile = blockIdx.x; tile < NPTS / 64; tile += gridDim.x) {
        // ---- encode 64 points into A0 (rows padded to 48 with one zero col) ----
        if (tid < 64) {
            int p = tid;
            size_t pg = (size_t)tile * 64 + p;
            float xv = x[pg * 3 + 0], yv = x[pg * 3 + 1], zv = x[pg * 3 + 2];
            int ix = min(max((int)((xv + 1.f) * 0.5f * (RES - 1)), 0), RES - 1);
            int iy = min(max((int)((yv + 1.f) * 0.5f * (RES - 1)), 0), RES - 1);
            int iz = min(max((int)((zv + 1.f) * 0.5f * (RES - 1)), 0), RES - 1);
            __half* arow = A0 + p * LDW0;
#pragma unroll
            for (int rr = 0; rr < 8; rr++) {
                float f = fxy[rr * (RES * RES) + iy * RES + ix]
                        + fxz[rr * (RES * RES) + iz * RES + ix]
                        + fyz[rr * (RES * RES) + iz * RES + iy];
                arow[rr] = __float2half(f);
            }
            arow[8]  = __float2half(xv);
            arow[9]  = __float2half(yv);
            arow[10] = __float2half(zv);
            float fr = 1.f;
#pragma unroll
            for (int l = 0; l < 6; l++) {
                int base = 11 + l * 6;
                arow[base + 0] = __float2half(sinf(xv * fr));
                arow[base + 1] = __float2half(sinf(yv * fr));
                arow[base + 2] = __float2half(sinf(zv * fr));
                arow[base + 3] = __float2half(cosf(xv * fr));
                arow[base + 4] = __float2half(cosf(yv * fr));
                arow[base + 5] = __float2half(cosf(zv * fr));
                fr *= 2.f;
            }
            arow[47] = __float2half(0.f);
        }
        __syncthreads();

        // ---- layer 0: A0(64x48) @ W0 -> H ----
        float acc[16][4];
#pragma unroll
        for (int t = 0; t < 16; t++) acc[t][0] = acc[t][1] = acc[t][2] = acc[t][3] = 0.f;
        gemm_warp<48>(A0, LDW0, Wt0, LDW0, m0, n0, lane, acc);
        __syncthreads();  // previous tile's layer-1 reads of H are done; safe to overwrite
#pragma unroll
        for (int t = 0; t < 16; t++) {
            int nc = n0 + t * 8 + r * 2;
            float bb0 = b0s[nc], bb1 = b0s[nc + 1];
            float f0 = fmaxf(acc[t][0] + bb0, 0.f), f1 = fmaxf(acc[t][1] + bb1, 0.f);
            float f2 = fmaxf(acc[t][2] + bb0, 0.f), f3 = fmaxf(acc[t][3] + bb1, 0.f);
            *(__half2*)&H[(m0 + g) * LDW + nc]     = __floats2half2_rn(f0, f1);
            *(__half2*)&H[(m0 + g + 8) * LDW + nc] = __floats2half2_rn(f2, f3);
        }
        __syncthreads();

        // ---- layer 1: H(64x256) @ W1 -> g_h1 ----
#pragma unroll
        for (int t = 0; t < 16; t++) acc[t][0] = acc[t][1] = acc[t][2] = acc[t][3] = 0.f;
        gemm_warp<256>(H, LDW, Wt1, LDW, m0, n0, lane, acc);
        __half* outp = h1_out + (size_t)tile * 64 * 256;
#pragma unroll
        for (int t = 0; t < 16; t++) {
            int nc = n0 + t * 8 + r * 2;
            float bb0 = b1s[nc], bb1 = b1s[nc + 1];
            float f0 = fmaxf(acc[t][0] + bb0, 0.f), f1 = fmaxf(acc[t][1] + bb1, 0.f);
            float f2 = fmaxf(acc[t][2] + bb0, 0.f), f3 = fmaxf(acc[t][3] + bb1, 0.f);
            *(__half2*)&outp[(size_t)(m0 + g) * 256 + nc]     = __floats2half2_rn(f0, f1);
            *(__half2*)&outp[(size_t)(m0 + g + 8) * 256 + nc] = __floats2half2_rn(f2, f3);
        }
    }
}

// ============================================================================
// K2: one hidden layer (256->256, ReLU). 512 threads, M-tile = 128, persistent.
// A streamed straight from global (fp16), weights resident in smem.
// ============================================================================
__global__ void __launch_bounds__(512, 1) k_layer(
    const float* __restrict__ W, const float* __restrict__ b,
    const __half* __restrict__ in, __half* __restrict__ outh) {
    __half* Wt = (__half*)smem_raw;             // 256*264
    float*  bs = (float*)(Wt + 256 * LDW);      // 256

    const int tid = threadIdx.x;
    for (int i = tid; i < 256 * 256; i += 512) {
        int k = i >> 8, n = i & 255;
        Wt[n * LDW + k] = __float2half(W[k * 256 + n]);
    }
    if (tid < 256) bs[tid] = b[tid];
    __syncthreads();

    const int wid = tid >> 5, lane = tid & 31;
    const int m0 = (wid >> 1) * 16, n0 = (wid & 1) * 128;
    const int g = lane >> 2, r = lane & 3;

    for (int tile = blockIdx.x; tile < NPTS / 128; tile += gridDim.x) {
        const __half* A = in + (size_t)tile * 128 * 256;
        float acc[16][4];
#pragma unroll
        for (int t = 0; t < 16; t++) acc[t][0] = acc[t][1] = acc[t][2] = acc[t][3] = 0.f;
        gemm_warp<256>(A, 256, Wt, LDW, m0, n0, lane, acc);
        __half* outp = outh + (size_t)tile * 128 * 256;
#pragma unroll
        for (int t = 0; t < 16; t++) {
            int nc = n0 + t * 8 + r * 2;
            float bb0 = bs[nc], bb1 = bs[nc + 1];
            float f0 = fmaxf(acc[t][0] + bb0, 0.f), f1 = fmaxf(acc[t][1] + bb1, 0.f);
            float f2 = fmaxf(acc[t][2] + bb0, 0.f), f3 = fmaxf(acc[t][3] + bb1, 0.f);
            *(__half2*)&outp[(size_t)(m0 + g) * 256 + nc]     = __floats2half2_rn(f0, f1);
            *(__half2*)&outp[(size_t)(m0 + g + 8) * 256 + nc] = __floats2half2_rn(f2, f3);
        }
    }
}

// ============================================================================
// K3: layer 3 (256->256 ReLU) + heads (sigma softplus, rgb sigmoid).
// 512 threads, M-tile = 128, persistent. h3 staged in smem for the head dots.
// ============================================================================
__global__ void __launch_bounds__(512, 1) k_l3_heads(
    const float* __restrict__ W3, const float* __restrict__ b3,
    const float* __restrict__ Wsig, const float* __restrict__ bsig,
    const float* __restrict__ Wrgb, const float* __restrict__ brgb,
    const __half* __restrict__ in, float* __restrict__ out) {
    __half* Wt  = (__half*)smem_raw;             // 256*264
    float*  bs  = (float*)(Wt + 256 * LDW);      // 256
    float*  Wh  = bs + 256;                      // 256*4 (layout [k*4+j], j: 0..2 rgb, 3 sigma)
    float*  bh  = Wh + 1024;                     // 4
    __half* H3  = (__half*)(bh + 4);             // 128*264

    const int tid = threadIdx.x;
    for (int i = tid; i < 256 * 256; i += 512) {
        int k = i >> 8, n = i & 255;
        Wt[n * LDW + k] = __float2half(W3[k * 256 + n]);
    }
    if (tid < 256) bs[tid] = b3[tid];
    for (int i = tid; i < 1024; i += 512) {
        int k = i >> 2, j = i & 3;
        Wh[i] = (j < 3) ? Wrgb[k * 3 + j] : Wsig[k];
    }
    if (tid < 4) bh[tid] = (tid < 3) ? brgb[tid] : bsig[0];
    __syncthreads();

    const int wid = tid >> 5, lane = tid & 31;
    const int m0 = (wid >> 1) * 16, n0 = (wid & 1) * 128;
    const int g = lane >> 2, r = lane & 3;

    for (int tile = blockIdx.x; tile < NPTS / 128; tile += gridDim.x) {
        const __half* A = in + (size_t)tile * 128 * 256;
        float acc[16][4];
#pragma unroll
        for (int t = 0; t < 16; t++) acc[t][0] = acc[t][1] = acc[t][2] = acc[t][3] = 0.f;
        gemm_warp<256>(A, 256, Wt, LDW, m0, n0, lane, acc);

        __syncthreads();  // previous tile's head reads of H3 done
#pragma unroll
        for (int t = 0; t < 16; t++) {
            int nc = n0 + t * 8 + r * 2;
            float bb0 = bs[nc], bb1 = bs[nc + 1];
            float f0 = fmaxf(acc[t][0] + bb0, 0.f), f1 = fmaxf(acc[t][1] + bb1, 0.f);
            float f2 = fmaxf(acc[t][2] + bb0, 0.f), f3 = fmaxf(acc[t][3] + bb1, 0.f);
            *(__half2*)&H3[(m0 + g) * LDW + nc]     = __floats2half2_rn(f0, f1);
            *(__half2*)&H3[(m0 + g + 8) * LDW + nc] = __floats2half2_rn(f2, f3);
        }
        __syncthreads();

        // heads: 512 threads = 128 points x 4 outputs
        {
            int p = tid >> 2, j = tid & 3;
            float v = bh[j];
            const __half* hr = H3 + p * LDW;
#pragma unroll 8
            for (int k = 0; k < 256; k++)
                v += __half2float(hr[k]) * Wh[k * 4 + j];
            size_t pg = (size_t)tile * 128 + p;
            if (j < 3)
                out[pg * 3 + j] = 1.f / (1.f + expf(-v));               // sigmoid
            else
                out[(size_t)3 * NPTS + pg] = (v > 20.f) ? v : log1pf(expf(v));  // softplus
        }
    }
}

// ============================================================================
extern "C" void kernel_launch(void* const* d_in, const int* in_sizes, int n_in,
                              void* d_out, int out_size) {
    const float* x    = (const float*)d_in[0];
    const float* fxy  = (const float*)d_in[1];
    const float* fxz  = (const float*)d_in[2];
    const float* fyz  = (const float*)d_in[3];
    const float* W0   = (const float*)d_in[4];
    const float* b0   = (const float*)d_in[5];
    const float* W1   = (const float*)d_in[6];
    const float* b1   = (const float*)d_in[7];
    const float* W2   = (const float*)d_in[8];
    const float* b2   = (const float*)d_in[9];
    const float* W3   = (const float*)d_in[10];
    const float* b3   = (const float*)d_in[11];
    const float* Wsig = (const float*)d_in[12];
    const float* bsig = (const float*)d_in[13];
    const float* Wrgb = (const float*)d_in[14];
    const float* brgb = (const float*)d_in[15];

    void *p1, *p2;
    cudaGetSymbolAddress(&p1, g_h1);
    cudaGetSymbolAddress(&p2, g_h2);

    int nsm = 148;
    cudaDeviceGetAttribute(&nsm, cudaDevAttrMultiProcessorCount, 0);

    const size_t S1 = 256 * LDW0 * 2 + 256 * LDW * 2 + 2 * 256 * 4 + 64 * LDW0 * 2 + 64 * LDW * 2;
    const size_t S2 = 256 * LDW * 2 + 256 * 4;
    const size_t S3 = 256 * LDW * 2 + 256 * 4 + 1024 * 4 + 4 * 4 + 128 * LDW * 2;

    cudaFuncSetAttribute(k_enc01,    cudaFuncAttributeMaxDynamicSharedMemorySize, (int)S1);
    cudaFuncSetAttribute(k_layer,    cudaFuncAttributeMaxDynamicSharedMemorySize, (int)S2);
    cudaFuncSetAttribute(k_l3_heads, cudaFuncAttributeMaxDynamicSharedMemorySize, (int)S3);

    k_enc01<<<nsm, 256, S1>>>(x, fxy, fxz, fyz, W0, b0, W1, b1, (__half*)p1);
    k_layer<<<nsm, 512, S2>>>(W2, b2, (const __half*)p1, (__half*)p2);
    k_l3_heads<<<nsm, 512, S3>>>(W3, b3, Wsig, bsig, Wrgb, brgb, (const __half*)p2, (float*)d_out);
}

// round 4
// speedup vs baseline: 1.0005x; 1.0005x over previous
#include <cuda_runtime.h>
#include <cuda_fp16.h>
#include <math.h>

#define NPTS (1 << 20)
#define RES 128
#define LDW 264   // padded K-stride (halves) for 256-wide operands: bank-conflict-free
#define LDW0 56   // padded K-stride for the 48-wide layer-0 input

// Scratch activations (device globals: allocation-free per harness rules)
static __device__ __half g_h1[(size_t)NPTS * 256];
static __device__ __half g_h2[(size_t)NPTS * 256];

__device__ __forceinline__ void mma16816(float c[4], const unsigned a[4], const unsigned b[2]) {
    asm volatile(
        "mma.sync.aligned.m16n8k16.row.col.f32.f16.f16.f32 "
        "{%0,%1,%2,%3},{%4,%5,%6,%7},{%8,%9},{%0,%1,%2,%3};\n"
        : "+f"(c[0]), "+f"(c[1]), "+f"(c[2]), "+f"(c[3])
        : "r"(a[0]), "r"(a[1]), "r"(a[2]), "r"(a[3]), "r"(b[0]), "r"(b[1]));
}

// Warp computes a 16(m) x 128(n) tile: A row-major (lda in halves), W transposed
// in smem as Wt[n][k] row-major with stride ldw (= col-major B for mma).
template <int KDIM>
__device__ __forceinline__ void gemm_warp(const __half* A, int lda,
                                          const __half* Wt, int ldw,
                                          int m0, int n0, int lane,
                                          float acc[16][4]) {
    const int g = lane >> 2, r = lane & 3;
    for (int k0 = 0; k0 < KDIM; k0 += 16) {
        unsigned a[4];
        const __half* ap = A + (size_t)(m0 + g) * lda + k0 + r * 2;
        a[0] = *(const unsigned*)(ap);
        a[1] = *(const unsigned*)(ap + (size_t)8 * lda);
        a[2] = *(const unsigned*)(ap + 8);
        a[3] = *(const unsigned*)(ap + (size_t)8 * lda + 8);
#pragma unroll
        for (int t = 0; t < 16; t++) {
            const __half* bp = Wt + (size_t)(n0 + t * 8 + g) * ldw + k0 + r * 2;
            unsigned b[2];
            b[0] = *(const unsigned*)(bp);
            b[1] = *(const unsigned*)(bp + 8);
            mma16816(acc[t], a, b);
        }
    }
}

// ============================================================================
// K1: encode (tri-plane gather + PE) + layer0 (47->256) + layer1 (256->256)
// 256 threads, M-tile = 64, persistent.
// ============================================================================
extern __shared__ char smem_raw[];

__global__ void __launch_bounds__(256, 1) k_enc01(
    const float* __restrict__ x,
    const float* __restrict__ fxy, const float* __restrict__ fxz, const float* __restrict__ fyz,
    const float* __restrict__ W0, const float* __restrict__ b0,
    const float* __restrict__ W1, const float* __restrict__ b1,
    __half* __restrict__ h1_out) {
    __half* Wt0 = (__half*)smem_raw;                 // 256*56 halves
    __half* Wt1 = Wt0 + 256 * LDW0;                  // 256*264 halves
    float*  b0s = (float*)(Wt1 + 256 * LDW);         // 256 f32
    float*  b1s = b0s + 256;                         // 256 f32
    __half* A0  = (__half*)(b1s + 256);              // 64*56 halves
    __half* H   = A0 + 64 * LDW0;                    // 64*264 halves

    const int tid = threadIdx.x;

    // One-time: transpose weights to fp16 smem, load biases.
    for (int i = tid; i < 48 * 256; i += 256) {
        int k = i >> 8, n = i & 255;
        Wt0[n * LDW0 + k] = __float2half(k < 47 ? W0[k * 256 + n] : 0.f);
    }
    for (int i = tid; i < 256 * 256; i += 256) {
        int k = i >> 8, n = i & 255;
        Wt1[n * LDW + k] = __float2half(W1[k * 256 + n]);
    }
    if (tid < 256) { b0s[tid] = b0[tid]; b1s[tid] = b1[tid]; }
    __syncthreads();

    const int wid = tid >> 5, lane = tid & 31;
    const int m0 = (wid >> 1) * 16, n0 = (wid & 1) * 128;
    const int g = lane >> 2, r = lane & 3;

    for (int tile = blockIdx.x; tile < NPTS / 64; tile += gridDim.x) {
        // ---- encode 64 points into A0 (rows padded to 48 with one zero col) ----
        if (tid < 64) {
            int p = tid;
            size_t pg = (size_t)tile * 64 + p;
            float xv = x[pg * 3 + 0], yv = x[pg * 3 + 1], zv = x[pg * 3 + 2];
            int ix = min(max((int)((xv + 1.f) * 0.5f * (RES - 1)), 0), RES - 1);
            int iy = min(max((int)((yv + 1.f) * 0.5f * (RES - 1)), 0), RES - 1);
            int iz = min(max((int)((zv + 1.f) * 0.5f * (RES - 1)), 0), RES - 1);
            __half* arow = A0 + p * LDW0;
#pragma unroll
            for (int rr = 0; rr < 8; rr++) {
                float f = fxy[rr * (RES * RES) + iy * RES + ix]
                        + fxz[rr * (RES * RES) + iz * RES + ix]
                        + fyz[rr * (RES * RES) + iz * RES + iy];
                arow[rr] = __float2half(f);
            }
            arow[8]  = __float2half(xv);
            arow[9]  = __float2half(yv);
            arow[10] = __float2half(zv);
            float fr = 1.f;
#pragma unroll
            for (int l = 0; l < 6; l++) {
                int base = 11 + l * 6;
                arow[base + 0] = __float2half(sinf(xv * fr));
                arow[base + 1] = __float2half(sinf(yv * fr));
                arow[base + 2] = __float2half(sinf(zv * fr));
                arow[base + 3] = __float2half(cosf(xv * fr));
                arow[base + 4] = __float2half(cosf(yv * fr));
                arow[base + 5] = __float2half(cosf(zv * fr));
                fr *= 2.f;
            }
            arow[47] = __float2half(0.f);
        }
        __syncthreads();

        // ---- layer 0: A0(64x48) @ W0 -> H ----
        float acc[16][4];
#pragma unroll
        for (int t = 0; t < 16; t++) acc[t][0] = acc[t][1] = acc[t][2] = acc[t][3] = 0.f;
        gemm_warp<48>(A0, LDW0, Wt0, LDW0, m0, n0, lane, acc);
        __syncthreads();  // previous tile's layer-1 reads of H are done; safe to overwrite
#pragma unroll
        for (int t = 0; t < 16; t++) {
            int nc = n0 + t * 8 + r * 2;
            float bb0 = b0s[nc], bb1 = b0s[nc + 1];
            float f0 = fmaxf(acc[t][0] + bb0, 0.f), f1 = fmaxf(acc[t][1] + bb1, 0.f);
            float f2 = fmaxf(acc[t][2] + bb0, 0.f), f3 = fmaxf(acc[t][3] + bb1, 0.f);
            *(__half2*)&H[(m0 + g) * LDW + nc]     = __floats2half2_rn(f0, f1);
            *(__half2*)&H[(m0 + g + 8) * LDW + nc] = __floats2half2_rn(f2, f3);
        }
        __syncthreads();

        // ---- layer 1: H(64x256) @ W1 -> g_h1 ----
#pragma unroll
        for (int t = 0; t < 16; t++) acc[t][0] = acc[t][1] = acc[t][2] = acc[t][3] = 0.f;
        gemm_warp<256>(H, LDW, Wt1, LDW, m0, n0, lane, acc);
        __half* outp = h1_out + (size_t)tile * 64 * 256;
#pragma unroll
        for (int t = 0; t < 16; t++) {
            int nc = n0 + t * 8 + r * 2;
            float bb0 = b1s[nc], bb1 = b1s[nc + 1];
            float f0 = fmaxf(acc[t][0] + bb0, 0.f), f1 = fmaxf(acc[t][1] + bb1, 0.f);
            float f2 = fmaxf(acc[t][2] + bb0, 0.f), f3 = fmaxf(acc[t][3] + bb1, 0.f);
            *(__half2*)&outp[(size_t)(m0 + g) * 256 + nc]     = __floats2half2_rn(f0, f1);
            *(__half2*)&outp[(size_t)(m0 + g + 8) * 256 + nc] = __floats2half2_rn(f2, f3);
        }
    }
}

// ============================================================================
// K2: one hidden layer (256->256, ReLU). 512 threads, M-tile = 128, persistent.
// A streamed straight from global (fp16), weights resident in smem.
// ============================================================================
__global__ void __launch_bounds__(512, 1) k_layer(
    const float* __restrict__ W, const float* __restrict__ b,
    const __half* __restrict__ in, __half* __restrict__ outh) {
    __half* Wt = (__half*)smem_raw;             // 256*264
    float*  bs = (float*)(Wt + 256 * LDW);      // 256

    const int tid = threadIdx.x;
    for (int i = tid; i < 256 * 256; i += 512) {
        int k = i >> 8, n = i & 255;
        Wt[n * LDW + k] = __float2half(W[k * 256 + n]);
    }
    if (tid < 256) bs[tid] = b[tid];
    __syncthreads();

    const int wid = tid >> 5, lane = tid & 31;
    const int m0 = (wid >> 1) * 16, n0 = (wid & 1) * 128;
    const int g = lane >> 2, r = lane & 3;

    for (int tile = blockIdx.x; tile < NPTS / 128; tile += gridDim.x) {
        const __half* A = in + (size_t)tile * 128 * 256;
        float acc[16][4];
#pragma unroll
        for (int t = 0; t < 16; t++) acc[t][0] = acc[t][1] = acc[t][2] = acc[t][3] = 0.f;
        gemm_warp<256>(A, 256, Wt, LDW, m0, n0, lane, acc);
        __half* outp = outh + (size_t)tile * 128 * 256;
#pragma unroll
        for (int t = 0; t < 16; t++) {
            int nc = n0 + t * 8 + r * 2;
            float bb0 = bs[nc], bb1 = bs[nc + 1];
            float f0 = fmaxf(acc[t][0] + bb0, 0.f), f1 = fmaxf(acc[t][1] + bb1, 0.f);
            float f2 = fmaxf(acc[t][2] + bb0, 0.f), f3 = fmaxf(acc[t][3] + bb1, 0.f);
            *(__half2*)&outp[(size_t)(m0 + g) * 256 + nc]     = __floats2half2_rn(f0, f1);
            *(__half2*)&outp[(size_t)(m0 + g + 8) * 256 + nc] = __floats2half2_rn(f2, f3);
        }
    }
}

// ============================================================================
// K3: layer 3 (256->256 ReLU) + heads (sigma softplus, rgb sigmoid).
// 512 threads, M-tile = 128, persistent. h3 staged in smem for the head dots.
// ============================================================================
__global__ void __launch_bounds__(512, 1) k_l3_heads(
    const float* __restrict__ W3, const float* __restrict__ b3,
    const float* __restrict__ Wsig, const float* __restrict__ bsig,
    const float* __restrict__ Wrgb, const float* __restrict__ brgb,
    const __half* __restrict__ in, float* __restrict__ out) {
    __half* Wt  = (__half*)smem_raw;             // 256*264
    float*  bs  = (float*)(Wt + 256 * LDW);      // 256
    float*  Wh  = bs + 256;                      // 256*4 (layout [k*4+j], j: 0..2 rgb, 3 sigma)
    float*  bh  = Wh + 1024;                     // 4
    __half* H3  = (__half*)(bh + 4);             // 128*264

    const int tid = threadIdx.x;
    for (int i = tid; i < 256 * 256; i += 512) {
        int k = i >> 8, n = i & 255;
        Wt[n * LDW + k] = __float2half(W3[k * 256 + n]);
    }
    if (tid < 256) bs[tid] = b3[tid];
    for (int i = tid; i < 1024; i += 512) {
        int k = i >> 2, j = i & 3;
        Wh[i] = (j < 3) ? Wrgb[k * 3 + j] : Wsig[k];
    }
    if (tid < 4) bh[tid] = (tid < 3) ? brgb[tid] : bsig[0];
    __syncthreads();

    const int wid = tid >> 5, lane = tid & 31;
    const int m0 = (wid >> 1) * 16, n0 = (wid & 1) * 128;
    const int g = lane >> 2, r = lane & 3;

    for (int tile = blockIdx.x; tile < NPTS / 128; tile += gridDim.x) {
        const __half* A = in + (size_t)tile * 128 * 256;
        float acc[16][4];
#pragma unroll
        for (int t = 0; t < 16; t++) acc[t][0] = acc[t][1] = acc[t][2] = acc[t][3] = 0.f;
        gemm_warp<256>(A, 256, Wt, LDW, m0, n0, lane, acc);

        __syncthreads();  // previous tile's head reads of H3 done
#pragma unroll
        for (int t = 0; t < 16; t++) {
            int nc = n0 + t * 8 + r * 2;
            float bb0 = bs[nc], bb1 = bs[nc + 1];
            float f0 = fmaxf(acc[t][0] + bb0, 0.f), f1 = fmaxf(acc[t][1] + bb1, 0.f);
            float f2 = fmaxf(acc[t][2] + bb0, 0.f), f3 = fmaxf(acc[t][3] + bb1, 0.f);
            *(__half2*)&H3[(m0 + g) * LDW + nc]     = __floats2half2_rn(f0, f1);
            *(__half2*)&H3[(m0 + g + 8) * LDW + nc] = __floats2half2_rn(f2, f3);
        }
        __syncthreads();

        // heads: 512 threads = 128 points x 4 outputs
        {
            int p = tid >> 2, j = tid & 3;
            float v = bh[j];
            const __half* hr = H3 + p * LDW;
#pragma unroll 8
            for (int k = 0; k < 256; k++)
                v += __half2float(hr[k]) * Wh[k * 4 + j];
            size_t pg = (size_t)tile * 128 + p;
            if (j < 3)
                out[pg * 3 + j] = 1.f / (1.f + expf(-v));               // sigmoid
            else
                out[(size_t)3 * NPTS + pg] = (v > 20.f) ? v : log1pf(expf(v));  // softplus
        }
    }
}

// ============================================================================
extern "C" void kernel_launch(void* const* d_in, const int* in_sizes, int n_in,
                              void* d_out, int out_size) {
    const float* x    = (const float*)d_in[0];
    const float* fxy  = (const float*)d_in[1];
    const float* fxz  = (const float*)d_in[2];
    const float* fyz  = (const float*)d_in[3];
    const float* W0   = (const float*)d_in[4];
    const float* b0   = (const float*)d_in[5];
    const float* W1   = (const float*)d_in[6];
    const float* b1   = (const float*)d_in[7];
    const float* W2   = (const float*)d_in[8];
    const float* b2   = (const float*)d_in[9];
    const float* W3   = (const float*)d_in[10];
    const float* b3   = (const float*)d_in[11];
    const float* Wsig = (const float*)d_in[12];
    const float* bsig = (const float*)d_in[13];
    const float* Wrgb = (const float*)d_in[14];
    const float* brgb = (const float*)d_in[15];

    void *p1, *p2;
    cudaGetSymbolAddress(&p1, g_h1);
    cudaGetSymbolAddress(&p2, g_h2);

    int nsm = 148;
    cudaDeviceGetAttribute(&nsm, cudaDevAttrMultiProcessorCount, 0);

    const size_t S1 = 256 * LDW0 * 2 + 256 * LDW * 2 + 2 * 256 * 4 + 64 * LDW0 * 2 + 64 * LDW * 2;
    const size_t S2 = 256 * LDW * 2 + 256 * 4;
    const size_t S3 = 256 * LDW * 2 + 256 * 4 + 1024 * 4 + 4 * 4 + 128 * LDW * 2;

    cudaFuncSetAttribute(k_enc01,    cudaFuncAttributeMaxDynamicSharedMemorySize, (int)S1);
    cudaFuncSetAttribute(k_layer,    cudaFuncAttributeMaxDynamicSharedMemorySize, (int)S2);
    cudaFuncSetAttribute(k_l3_heads, cudaFuncAttributeMaxDynamicSharedMemorySize, (int)S3);

    k_enc01<<<nsm, 256, S1>>>(x, fxy, fxz, fyz, W0, b0, W1, b1, (__half*)p1);
    k_layer<<<nsm, 512, S2>>>(W2, b2, (const __half*)p1, (__half*)p2);
    k_l3_heads<<<nsm, 512, S3>>>(W3, b3, Wsig, bsig, Wrgb, brgb, (const __half*)p2, (float*)d_out);
}

// round 8
// speedup vs baseline: 1.1459x; 1.1453x over previous
#include <cuda_runtime.h>
#include <cuda_fp16.h>
#include <math.h>
#include <cstdint>

#define NPTS (1 << 20)
#define RES 128
#define LDW 264   // K-stride (halves) for 256-wide operands: LDSM conflict-free (4j rot)
#define LDW0 56   // K-stride for the 48-wide layer-0 input: LDSM conflict-free (28j rot)

// Scratch activations (device globals: allocation-free per harness rules)
static __device__ __align__(16) __half g_h1[(size_t)NPTS * 256];
static __device__ __align__(16) __half g_h2[(size_t)NPTS * 256];

__device__ __forceinline__ uint32_t smem_u32(const void* p) {
    uint32_t a;
    asm("{ .reg .u64 t; cvta.to.shared.u64 t, %1; cvt.u32.u64 %0, t; }" : "=r"(a) : "l"(p));
    return a;
}

__device__ __forceinline__ void mma16816(float c[4], const unsigned a[4], const unsigned b[2]) {
    asm volatile(
        "mma.sync.aligned.m16n8k16.row.col.f32.f16.f16.f32 "
        "{%0,%1,%2,%3},{%4,%5,%6,%7},{%8,%9},{%0,%1,%2,%3};\n"
        : "+f"(c[0]), "+f"(c[1]), "+f"(c[2]), "+f"(c[3])
        : "r"(a[0]), "r"(a[1]), "r"(a[2]), "r"(a[3]), "r"(b[0]), "r"(b[1]));
}

__device__ __forceinline__ void ldsm4(unsigned& r0, unsigned& r1, unsigned& r2, unsigned& r3,
                                      uint32_t addr) {
    asm volatile("ldmatrix.sync.aligned.m8n8.x4.shared.b16 {%0,%1,%2,%3}, [%4];"
                 : "=r"(r0), "=r"(r1), "=r"(r2), "=r"(r3) : "r"(addr));
}

// Warp-level 16(m) x 128(n) x KDIM GEMM. A row-major in smem (stride LDA halves),
// B = Wt[n][k] row-major (stride LDB halves) == col-major operand for mma.
// All fragments via ldmatrix.x4.
template <int KDIM, int LDA, int LDB>
__device__ __forceinline__ void gemm_ldsm(uint32_t aA, uint32_t aB,
                                          int m0, int n0, int lane, float acc[16][4]) {
    const int q = lane >> 3, t7 = lane & 7;
    // A x4: lanes 0-7: rows m0..+7 @k0 | 8-15: rows m0+8..+15 @k0 | 16-23: m0..+7 @k0+8 | 24-31: +8,+8
    uint32_t a_addr = aA + (uint32_t)(((m0 + (q & 1) * 8 + t7) * LDA + (q >> 1) * 8) * 2);
    // B x4 (2 n-tiles): lanes 0-7: rows nt*8.. @k0 | 8-15: same rows @k0+8 | 16-31: rows (nt+1)*8..
    uint32_t b_base = aB + (uint32_t)(((n0 + (q >> 1) * 8 + t7) * LDB + (q & 1) * 8) * 2);
#pragma unroll
    for (int k0 = 0; k0 < KDIM; k0 += 16) {
        unsigned a[4];
        ldsm4(a[0], a[1], a[2], a[3], a_addr);
        a_addr += 32;
        uint32_t b_addr = b_base;
#pragma unroll
        for (int nt = 0; nt < 16; nt += 2) {
            unsigned b[4];
            ldsm4(b[0], b[1], b[2], b[3], b_addr);
            b_addr += 16 * LDB * 2;
            mma16816(acc[nt],     a, &b[0]);
            mma16816(acc[nt + 1], a, &b[2]);
        }
        b_base += 32;
    }
}

extern __shared__ char smem_raw[];

// ============================================================================
// K0: encode (tri-plane gather + PE, 4 threads/point) + layer0 (47->256)
// 256 threads, M-tile 64, persistent.
// ============================================================================
__global__ void __launch_bounds__(256, 1) k_enc0(
    const float* __restrict__ x,
    const float* __restrict__ fxy, const float* __restrict__ fxz, const float* __restrict__ fyz,
    const float* __restrict__ W0, const float* __restrict__ b0,
    __half* __restrict__ h_out) {
    __half* Wt0 = (__half*)smem_raw;                 // 256*56 halves
    float*  b0s = (float*)(Wt0 + 256 * LDW0);        // 256 f32
    __half* A0  = (__half*)(b0s + 256);              // 64*56 halves

    const int tid = threadIdx.x;

    for (int i = tid; i < 48 * 256; i += 256) {
        int k = i >> 8, n = i & 255;
        Wt0[n * LDW0 + k] = __float2half(k < 47 ? W0[k * 256 + n] : 0.f);
    }
    if (tid < 256) b0s[tid] = b0[tid];
    __syncthreads();

    const uint32_t aA0 = smem_u32(A0), aW0 = smem_u32(Wt0);
    const int wid = tid >> 5, lane = tid & 31;
    const int m0 = (wid >> 1) * 16, n0 = (wid & 1) * 128;
    const int g = lane >> 2, r = lane & 3;
    const int p = tid >> 2, c = tid & 3;   // encode: 4 threads per point

    for (int tile = blockIdx.x; tile < NPTS / 64; tile += gridDim.x) {
        {
            size_t pg = (size_t)tile * 64 + p;
            float xv = x[pg * 3 + 0], yv = x[pg * 3 + 1], zv = x[pg * 3 + 2];
            int ix = min(max((int)((xv + 1.f) * 0.5f * (RES - 1)), 0), RES - 1);
            int iy = min(max((int)((yv + 1.f) * 0.5f * (RES - 1)), 0), RES - 1);
            int iz = min(max((int)((zv + 1.f) * 0.5f * (RES - 1)), 0), RES - 1);
            __half* arow = A0 + p * LDW0;
            // 2 ranks per thread
#pragma unroll
            for (int rr = c * 2; rr < c * 2 + 2; rr++) {
                float f = fxy[rr * (RES * RES) + iy * RES + ix]
                        + fxz[rr * (RES * RES) + iz * RES + ix]
                        + fyz[rr * (RES * RES) + iz * RES + iy];
                arow[rr] = __float2half(f);
            }
            if (c < 3) {
                float cv = (c == 0) ? xv : (c == 1) ? yv : zv;
                float fr = 1.f;
#pragma unroll
                for (int l = 0; l < 6; l++) {
                    float s, co;
                    __sincosf(cv * fr, &s, &co);
                    arow[11 + l * 6 + c]     = __float2half(s);
                    arow[11 + l * 6 + 3 + c] = __float2half(co);
                    fr *= 2.f;
                }
            } else {
                arow[8]  = __float2half(xv);
                arow[9]  = __float2half(yv);
                arow[10] = __float2half(zv);
                arow[47] = __float2half(0.f);
            }
        }
        __syncthreads();

        float acc[16][4];
#pragma unroll
        for (int t = 0; t < 16; t++) acc[t][0] = acc[t][1] = acc[t][2] = acc[t][3] = 0.f;
        gemm_ldsm<48, LDW0, LDW0>(aA0, aW0, m0, n0, lane, acc);

        __half* outp = h_out + (size_t)tile * 64 * 256;
#pragma unroll
        for (int t = 0; t < 16; t++) {
            int nc = n0 + t * 8 + r * 2;
            float bb0 = b0s[nc], bb1 = b0s[nc + 1];
            float f0 = fmaxf(acc[t][0] + bb0, 0.f), f1 = fmaxf(acc[t][1] + bb1, 0.f);
            float f2 = fmaxf(acc[t][2] + bb0, 0.f), f3 = fmaxf(acc[t][3] + bb1, 0.f);
            *(__half2*)&outp[(size_t)(m0 + g) * 256 + nc]     = __floats2half2_rn(f0, f1);
            *(__half2*)&outp[(size_t)(m0 + g + 8) * 256 + nc] = __floats2half2_rn(f2, f3);
        }
        __syncthreads();  // A0 reused next tile
    }
}

// ============================================================================
// Hidden layer (256->256 ReLU), ldmatrix + mma.sync. 512 threads, M-tile 128,
// persistent, weights resident in SMEM, A tile staged in SMEM.
// HEADS=true fuses layer-3 + sigma/rgb heads; h3 staged into the A buffer.
// SMEM: Wt 256*264*2 = 135168 | bias 1024 | A 128*264*2 = 67584 | (Wh 4096 | bh 16)
// ============================================================================
#define SM_WT   0
#define SM_BS   (256 * LDW * 2)
#define SM_AT   (SM_BS + 1024)
#define SM_WH   (SM_AT + 128 * LDW * 2)
#define SM_BH   (SM_WH + 4096)
#define SM_TOT  (SM_BH + 16)

template <bool HEADS>
__global__ void __launch_bounds__(512, 1) k_layer(
    const float* __restrict__ W, const float* __restrict__ b,
    const float* __restrict__ Wsig, const float* __restrict__ bsig,
    const float* __restrict__ Wrgb, const float* __restrict__ brgb,
    const __half* __restrict__ in, void* __restrict__ outp) {
    __half* Wt = (__half*)(smem_raw + SM_WT);
    float*  bs = (float*)(smem_raw + SM_BS);
    __half* A  = (__half*)(smem_raw + SM_AT);
    float4* Wh4 = (float4*)(smem_raw + SM_WH);
    float*  bh  = (float*)(smem_raw + SM_BH);

    const int tid = threadIdx.x;

    for (int i = tid; i < 256 * 256; i += 512) {
        int k = i >> 8, n = i & 255;
        Wt[n * LDW + k] = __float2half(W[k * 256 + n]);
    }
    if (tid < 256) bs[tid] = b[tid];
    if (HEADS) {
        if (tid < 256)
            Wh4[tid] = make_float4(Wrgb[tid * 3 + 0], Wrgb[tid * 3 + 1],
                                   Wrgb[tid * 3 + 2], Wsig[tid]);
        if (tid < 3) bh[tid] = brgb[tid];
        if (tid == 3) bh[3] = bsig[0];
    }
    __syncthreads();

    const uint32_t aA = smem_u32(A), aW = smem_u32(Wt);
    const int wid = tid >> 5, lane = tid & 31;
    const int m0 = (wid >> 1) * 16, n0 = (wid & 1) * 128;
    const int g = lane >> 2, r = lane & 3;

    for (int tile = blockIdx.x; tile < NPTS / 128; tile += gridDim.x) {
        // ---- stage A tile: 128x256 fp16, row stride 264 (vectorized, conflict-free) ----
        const uint4* src = (const uint4*)(in + (size_t)tile * 128 * 256);
        for (int v = tid; v < 4096; v += 512) {
            int m = v >> 5, k = (v & 31) << 3;
            *(uint4*)&A[m * LDW + k] = src[v];
        }
        __syncthreads();

        float acc[16][4];
#pragma unroll
        for (int t = 0; t < 16; t++) acc[t][0] = acc[t][1] = acc[t][2] = acc[t][3] = 0.f;
        gemm_ldsm<256, LDW, LDW>(aA, aW, m0, n0, lane, acc);

        if (!HEADS) {
            __half* orow = (__half*)outp + (size_t)tile * 128 * 256;
#pragma unroll
            for (int t = 0; t < 16; t++) {
                int nc = n0 + t * 8 + r * 2;
                float bb0 = bs[nc], bb1 = bs[nc + 1];
                float f0 = fmaxf(acc[t][0] + bb0, 0.f), f1 = fmaxf(acc[t][1] + bb1, 0.f);
                float f2 = fmaxf(acc[t][2] + bb0, 0.f), f3 = fmaxf(acc[t][3] + bb1, 0.f);
                *(__half2*)&orow[(size_t)(m0 + g) * 256 + nc]     = __floats2half2_rn(f0, f1);
                *(__half2*)&orow[(size_t)(m0 + g + 8) * 256 + nc] = __floats2half2_rn(f2, f3);
            }
            __syncthreads();  // all warps done reading A before next tile's copy
        } else {
            // h3 -> reuse the A buffer (all gemm reads of A finished after this sync)
            __syncthreads();
#pragma unroll
            for (int t = 0; t < 16; t++) {
                int nc = n0 + t * 8 + r * 2;
                float bb0 = bs[nc], bb1 = bs[nc + 1];
                float f0 = fmaxf(acc[t][0] + bb0, 0.f), f1 = fmaxf(acc[t][1] + bb1, 0.f);
                float f2 = fmaxf(acc[t][2] + bb0, 0.f), f3 = fmaxf(acc[t][3] + bb1, 0.f);
                *(__half2*)&A[(m0 + g) * LDW + nc]     = __floats2half2_rn(f0, f1);
                *(__half2*)&A[(m0 + g + 8) * LDW + nc] = __floats2half2_rn(f2, f3);
            }
            __syncthreads();

            // heads: 512 threads = 128 points x 4 outputs
            int p = tid >> 2, j = tid & 3;
            float v = bh[j];
            const __half* hr = A + p * LDW;
            const float* WhS = (const float*)Wh4;
#pragma unroll 8
            for (int k = 0; k < 256; k++)
                v += __half2float(hr[k]) * WhS[k * 4 + j];
            size_t pg = (size_t)tile * 128 + p;
            float* o = (float*)outp;
            if (j < 3)
                o[pg * 3 + j] = 1.f / (1.f + __expf(-v));
            else
                o[(size_t)3 * NPTS + pg] = (v > 20.f) ? v : log1pf(__expf(v));
            __syncthreads();  // head reads of A done before next tile's copy
        }
    }
}

// ============================================================================
extern "C" void kernel_launch(void* const* d_in, const int* in_sizes, int n_in,
                              void* d_out, int out_size) {
    const float* x    = (const float*)d_in[0];
    const float* fxy  = (const float*)d_in[1];
    const float* fxz  = (const float*)d_in[2];
    const float* fyz  = (const float*)d_in[3];
    const float* W0   = (const float*)d_in[4];
    const float* b0   = (const float*)d_in[5];
    const float* W1   = (const float*)d_in[6];
    const float* b1   = (const float*)d_in[7];
    const float* W2   = (const float*)d_in[8];
    const float* b2   = (const float*)d_in[9];
    const float* W3   = (const float*)d_in[10];
    const float* b3   = (const float*)d_in[11];
    const float* Wsig = (const float*)d_in[12];
    const float* bsig = (const float*)d_in[13];
    const float* Wrgb = (const float*)d_in[14];
    const float* brgb = (const float*)d_in[15];

    void *p1, *p2;
    cudaGetSymbolAddress(&p1, g_h1);
    cudaGetSymbolAddress(&p2, g_h2);

    int nsm = 148;
    cudaDeviceGetAttribute(&nsm, cudaDevAttrMultiProcessorCount, 0);

    const size_t S0 = 256 * LDW0 * 2 + 256 * 4 + 64 * LDW0 * 2;
    const size_t ST = SM_TOT;

    cudaFuncSetAttribute(k_enc0,          cudaFuncAttributeMaxDynamicSharedMemorySize, (int)S0);
    cudaFuncSetAttribute(k_layer<false>,  cudaFuncAttributeMaxDynamicSharedMemorySize, (int)ST);
    cudaFuncSetAttribute(k_layer<true>,   cudaFuncAttributeMaxDynamicSharedMemorySize, (int)ST);

    // encode + L0 -> h1
    k_enc0<<<nsm, 256, S0>>>(x, fxy, fxz, fyz, W0, b0, (__half*)p1);
    // L1: h1 -> h2
    k_layer<false><<<nsm, 512, ST>>>(W1, b1, nullptr, nullptr, nullptr, nullptr,
                                     (const __half*)p1, p2);
    // L2: h2 -> h1
    k_layer<false><<<nsm, 512, ST>>>(W2, b2, nullptr, nullptr, nullptr, nullptr,
                                     (const __half*)p2, p1);
    // L3 + heads: h1 -> out
    k_layer<true><<<nsm, 512, ST>>>(W3, b3, Wsig, bsig, Wrgb, brgb,
                                    (const __half*)p1, d_out);
}